// round 5
// baseline (speedup 1.0000x reference)
#include <cuda_runtime.h>
#include <math.h>
#include <float.h>

#define KF 32768
#define KI 16384
#define BB 16
#define HH 32
#define NROW (BB*HH)
#define NBPR 4                 // score blocks per row
#define GAMMA_C 0.3f
#define EPS_C 1e-6f
#define L2E 1.4426950408889634f

// ---- scratch (static device arrays; no allocations) ----
__device__ float g_R[BB * KF];     // rf at image positions, 0 off-image
__device__ float g_W[BB * KF];     // low_rf at image positions, 0 off-image
__device__ float g_I[BB * KF];     // 1 at image positions, 0 off-image
__device__ float g_mu[BB * 4];
__device__ float g_inv[BB * 4];
__device__ float g_part[NROW * NBPR * 4];  // per-block partials [row][blk][z,zi,p,q]
__device__ float g_ca[NROW];       // GAMMA * m_pos
__device__ float g_cb[NROW];       // GAMMA * m_neg

__device__ __forceinline__ float fast_ex2(float x) {
    float y;
    asm("ex2.approx.ftz.f32 %0, %1;" : "=f"(y) : "f"(x));
    return y;
}

// ============================================================
// Kernel 1: per-(batch,feature) stats. grid=64, block=256
// ============================================================
__global__ void __launch_bounds__(256) stats_kernel(
    const float* __restrict__ fC, const float* __restrict__ fA,
    const float* __restrict__ fD, const float* __restrict__ fB)
{
    const int bf = blockIdx.x;           // b*4 + f
    const int b = bf >> 2, f = bf & 3;
    const int tid = threadIdx.x;
    const float* base = (f == 0 ? fC : f == 1 ? fA : f == 2 ? fD : fB) + b * KI;
    const float4* P = (const float4*)base;

    float s = 0.f, s2 = 0.f;
#pragma unroll 4
    for (int j = tid; j < KI / 4; j += 256) {
        float4 v = P[j];
        s  += (v.x + v.y) + (v.z + v.w);
        s2 += (v.x*v.x + v.y*v.y) + (v.z*v.z + v.w*v.w);
    }
#pragma unroll
    for (int off = 16; off; off >>= 1) {
        s  += __shfl_down_sync(0xffffffffu, s,  off);
        s2 += __shfl_down_sync(0xffffffffu, s2, off);
    }
    __shared__ float r1[8], r2[8];
    const int lane = tid & 31, warp = tid >> 5;
    if (lane == 0) { r1[warp] = s; r2[warp] = s2; }
    __syncthreads();
    if (tid == 0) {
        s = 0.f; s2 = 0.f;
#pragma unroll
        for (int w = 0; w < 8; w++) { s += r1[w]; s2 += r2[w]; }
        float mu = s * (1.f / KI);
        float var = s2 * (1.f / KI) - mu * mu;
        float sd = sqrtf(fmaxf(var, 0.f));
        g_mu[bf] = mu;
        g_inv[bf] = 1.f / (sd + EPS_C);
    }
}

// ============================================================
// Kernel 2: mask scan + on-the-fly rf + pack R/W/I. grid=16, block=1024
// ============================================================
__global__ void __launch_bounds__(1024) pack_kernel(
    const float* __restrict__ fC, const float* __restrict__ fA,
    const float* __restrict__ fD, const float* __restrict__ fB,
    const int* __restrict__ mask)
{
    const int b = blockIdx.x;
    const int tid = threadIdx.x;
    const int lane = tid & 31, warp = tid >> 5;

    const float mu0 = g_mu[b*4+0], iv0 = g_inv[b*4+0];
    const float mu1 = g_mu[b*4+1], iv1 = g_inv[b*4+1];
    const float mu2 = g_mu[b*4+2], iv2 = g_inv[b*4+2];
    const float mu3 = g_mu[b*4+3], iv3 = g_inv[b*4+3];
    const float* pC = fC + b*KI;
    const float* pA = fA + b*KI;
    const float* pD = fD + b*KI;
    const float* pB = fB + b*KI;

    // --- load 32 mask bits per thread, count ---
    const int base = b * KF + tid * 32;
    int mbits[32];
    int cnt = 0;
#pragma unroll
    for (int i = 0; i < 32; i += 4) {
        int4 mm = *(const int4*)(mask + base + i);
        mbits[i] = mm.x; mbits[i+1] = mm.y; mbits[i+2] = mm.z; mbits[i+3] = mm.w;
        cnt += mm.x + mm.y + mm.z + mm.w;
    }
    // inclusive warp scan
    int inc = cnt;
#pragma unroll
    for (int off = 1; off < 32; off <<= 1) {
        int v = __shfl_up_sync(0xffffffffu, inc, off);
        if (lane >= off) inc += v;
    }
    __shared__ int wsum[32];
    if (lane == 31) wsum[warp] = inc;
    __syncthreads();
    if (tid < 32) {
        int v = wsum[tid];
        int ssum = v;
#pragma unroll
        for (int off = 1; off < 32; off <<= 1) {
            int u = __shfl_up_sync(0xffffffffu, ssum, off);
            if (tid >= off) ssum += u;
        }
        wsum[tid] = ssum - v;
    }
    __syncthreads();
    int r = wsum[warp] + inc - cnt;   // exclusive prefix = rank of first image pos

    float4* Rp = (float4*)(g_R + base);
    float4* Wp = (float4*)(g_W + base);
    float4* Ip = (float4*)(g_I + base);
#pragma unroll
    for (int c = 0; c < 8; c++) {
        float rv[4], wv[4], iv[4];
#pragma unroll
        for (int e = 0; e < 4; e++) {
            if (mbits[c*4 + e]) {
                float zc = (pC[r] - mu0) * iv0;
                float za = (pA[r] - mu1) * iv1;
                float zd = (pD[r] - mu2) * iv2;
                float zb = (pB[r] - mu3) * iv3;
                float Ct = fmaxf(zc, 0.f);
                float At = 1.f / (1.f + fast_ex2(-za * L2E));
                float Dt = 1.f / (1.f + fast_ex2(-zd * L2E));
                float Bt = 1.f / (1.f + fast_ex2(-zb * L2E));
                float denom = fmaxf(1.f + 0.5f * (Dt + Bt), EPS_C);
                float rf = Ct * At / denom;
                rv[e] = rf;
                wv[e] = fmaxf(1.f - rf, 0.f);
                iv[e] = 1.f;
                r++;
            } else {
                rv[e] = 0.f; wv[e] = 0.f; iv[e] = 0.f;
            }
        }
        Rp[c] = make_float4(rv[0], rv[1], rv[2], rv[3]);
        Wp[c] = make_float4(wv[0], wv[1], wv[2], wv[3]);
        Ip[c] = make_float4(iv[0], iv[1], iv[2], iv[3]);
    }
}

// ============================================================
// Kernel 3: score — predicate-free FMA softmax sums.
// grid = NROW*NBPR = 2048, block = 256. Each block: 2048 float4 segment.
// ============================================================
__global__ void __launch_bounds__(256) score_kernel(const float* __restrict__ attn)
{
    const int blk = blockIdx.x;
    const int row = blk >> 2;            // bh
    const int seg = blk & 3;
    const int b = row >> 5;
    const int tid = threadIdx.x;

    const float4* A = (const float4*)(attn + (size_t)row * KF) + seg * 2048;
    const float4* R = (const float4*)(g_R + (size_t)b * KF) + seg * 2048;
    const float4* W = (const float4*)(g_W + (size_t)b * KF) + seg * 2048;
    const float4* I = (const float4*)(g_I + (size_t)b * KF) + seg * 2048;

    float z = 0.f, zi = 0.f, p = 0.f, q = 0.f;

#pragma unroll
    for (int j = 0; j < 8; j++) {
        const int i = j * 256 + tid;
        float4 x = A[i];
        float4 rr = R[i];
        float4 ww = W[i];
        float4 ii = I[i];
        float e0 = fast_ex2(x.x * L2E);
        float e1 = fast_ex2(x.y * L2E);
        float e2 = fast_ex2(x.z * L2E);
        float e3 = fast_ex2(x.w * L2E);
        z  += (e0 + e1) + (e2 + e3);
        zi = fmaf(e0, ii.x, fmaf(e1, ii.y, fmaf(e2, ii.z, fmaf(e3, ii.w, zi))));
        p  = fmaf(e0, rr.x, fmaf(e1, rr.y, fmaf(e2, rr.z, fmaf(e3, rr.w, p))));
        q  = fmaf(e0, ww.x, fmaf(e1, ww.y, fmaf(e2, ww.z, fmaf(e3, ww.w, q))));
    }

#pragma unroll
    for (int off = 16; off; off >>= 1) {
        z  += __shfl_down_sync(0xffffffffu, z,  off);
        zi += __shfl_down_sync(0xffffffffu, zi, off);
        p  += __shfl_down_sync(0xffffffffu, p,  off);
        q  += __shfl_down_sync(0xffffffffu, q,  off);
    }
    __shared__ float sred[8][4];
    const int lane = tid & 31, warp = tid >> 5;
    if (lane == 0) {
        sred[warp][0] = z; sred[warp][1] = zi; sred[warp][2] = p; sred[warp][3] = q;
    }
    __syncthreads();
    if (tid == 0) {
        z = 0.f; zi = 0.f; p = 0.f; q = 0.f;
#pragma unroll
        for (int w = 0; w < 8; w++) {
            z += sred[w][0]; zi += sred[w][1]; p += sred[w][2]; q += sred[w][3];
        }
        float* dst = g_part + (size_t)blk * 4;
        dst[0] = z; dst[1] = zi; dst[2] = p; dst[3] = q;
    }
}

// ============================================================
// Kernel 4: finalize scores + top-7 selection. grid=1, block=512
// ============================================================
__global__ void __launch_bounds__(512) select_kernel()
{
    __shared__ float s_sp[NROW], s_sn[NROW];
    const int tid = threadIdx.x;

    // finalize: deterministic fixed-order combine of 4 partials per row
    {
        const float* pp = g_part + (size_t)tid * NBPR * 4;
        float z = 0.f, zi = 0.f, p = 0.f, q = 0.f;
#pragma unroll
        for (int k = 0; k < NBPR; k++) {
            z += pp[k*4+0]; zi += pp[k*4+1]; p += pp[k*4+2]; q += pp[k*4+3];
        }
        float d = fmaxf(zi / z, EPS_C);
        s_sp[tid] = (p / z) / d;
        s_sn[tid] = (q / z) / d;
    }
    __syncthreads();

    if (tid < BB) {
        const int b = tid;
        const int KH = 7;   // ceil(0.2*32)
        float sp[HH], sn[HH];
        bool selp[HH], seln[HH];
#pragma unroll
        for (int h = 0; h < HH; h++) {
            sp[h] = s_sp[b * HH + h];
            sn[h] = s_sn[b * HH + h];
            selp[h] = false; seln[h] = false;
        }
        for (int t = 0; t < KH; t++) {
            int best = -1; float bv = -FLT_MAX;
            for (int h = 0; h < HH; h++)
                if (!selp[h] && sp[h] > bv) { bv = sp[h]; best = h; }
            selp[best] = true;
        }
        bool mpos[HH];
#pragma unroll
        for (int h = 0; h < HH; h++) mpos[h] = selp[h] && (sp[h] > 0.f);

        float ns[HH];
#pragma unroll
        for (int h = 0; h < HH; h++) ns[h] = mpos[h] ? -FLT_MAX : sn[h];
        for (int t = 0; t < KH; t++) {
            int best = -1; float bv = -FLT_MAX;
            for (int h = 0; h < HH; h++)
                if (!seln[h] && ns[h] > bv) { bv = ns[h]; best = h; }
            if (best < 0) break;
            seln[best] = true;
        }
#pragma unroll
        for (int h = 0; h < HH; h++) {
            bool mneg = seln[h] && (ns[h] > 0.f) && !mpos[h];
            g_ca[b * HH + h] = mpos[h] ? GAMMA_C : 0.f;
            g_cb[b * HH + h] = mneg    ? GAMMA_C : 0.f;
        }
    }
}

// ============================================================
// Kernel 5: out = attn + a*R - c*W. grid=8192, block=256. Streaming stores.
// ============================================================
__global__ void __launch_bounds__(256) apply_kernel(const float* __restrict__ attn,
                                                    float* __restrict__ out)
{
    const int bh   = blockIdx.x >> 4;          // 16 blocks per row
    const int seg  = blockIdx.x & 15;
    const int base = bh * 8192 + seg * 512 + threadIdx.x;
    const int b    = bh >> 5;

    const float4* Ap = (const float4*)attn;
    float4* Op = (float4*)out;

    float4 x0 = Ap[base];
    float4 x1 = Ap[base + 256];
    float a = g_ca[bh];
    float c = g_cb[bh];

    if (a == 0.f && c == 0.f) {
        __stcs(&Op[base], x0);
        __stcs(&Op[base + 256], x1);
        return;
    }

    const int pidx = seg * 512 + threadIdx.x;
    const float4* R = (const float4*)(g_R + (size_t)b * KF);
    const float4* W = (const float4*)(g_W + (size_t)b * KF);
    float4 r0 = R[pidx];
    float4 r1 = R[pidx + 256];
    float4 w0 = W[pidx];
    float4 w1 = W[pidx + 256];

    float4 o0, o1;
    o0.x = fmaf(a, r0.x, fmaf(-c, w0.x, x0.x));
    o0.y = fmaf(a, r0.y, fmaf(-c, w0.y, x0.y));
    o0.z = fmaf(a, r0.z, fmaf(-c, w0.z, x0.z));
    o0.w = fmaf(a, r0.w, fmaf(-c, w0.w, x0.w));
    o1.x = fmaf(a, r1.x, fmaf(-c, w1.x, x1.x));
    o1.y = fmaf(a, r1.y, fmaf(-c, w1.y, x1.y));
    o1.z = fmaf(a, r1.z, fmaf(-c, w1.z, x1.z));
    o1.w = fmaf(a, r1.w, fmaf(-c, w1.w, x1.w));
    __stcs(&Op[base], o0);
    __stcs(&Op[base + 256], o1);
}

// ============================================================
extern "C" void kernel_launch(void* const* d_in, const int* in_sizes, int n_in,
                              void* d_out, int out_size)
{
    const float* attn = (const float*)d_in[0];
    const int*   mask = (const int*)  d_in[1];
    const float* fC   = (const float*)d_in[2];
    const float* fA   = (const float*)d_in[3];
    const float* fD   = (const float*)d_in[4];
    const float* fB   = (const float*)d_in[5];
    float* out = (float*)d_out;

    stats_kernel<<<BB * 4, 256>>>(fC, fA, fD, fB);
    pack_kernel<<<BB, 1024>>>(fC, fA, fD, fB, mask);
    score_kernel<<<NROW * NBPR, 256>>>(attn);
    select_kernel<<<1, 512>>>();
    apply_kernel<<<NROW * 16, 256>>>(attn, out);
}

// round 11
// speedup vs baseline: 1.1376x; 1.1376x over previous
#include <cuda_runtime.h>
#include <math.h>
#include <float.h>

#define KF 32768
#define KI 16384
#define BB 16
#define HH 32
#define NROW (BB*HH)
#define NSEG 16                // score segments per row
#define HPB 8                  // heads per score block
#define GAMMA_C 0.3f
#define EPS_C 1e-6f
#define L2E 1.4426950408889634f

// ---- scratch (static device arrays; no allocations) ----
__device__ float g_RI[BB * KF * 2];        // interleaved (rf, indicator) per position
__device__ float g_part[NROW * NSEG * 4];  // per (row,seg): zi, p, sm, pad
__device__ float g_ca[NROW];               // GAMMA * m_pos
__device__ float g_cb[NROW];               // GAMMA * m_neg

__device__ __forceinline__ float fast_ex2(float x) {
    float y;
    asm("ex2.approx.ftz.f32 %0, %1;" : "=f"(y) : "f"(x));
    return y;
}

struct F8 { float v[8]; };

// 256-bit global load with L2 evict_last (legal form: .v8.b32)
__device__ __forceinline__ F8 ldg256_evict_last(const float* p) {
    unsigned r0, r1, r2, r3, r4, r5, r6, r7;
    asm volatile("ld.global.L2::evict_last.v8.b32 {%0,%1,%2,%3,%4,%5,%6,%7}, [%8];"
                 : "=r"(r0), "=r"(r1), "=r"(r2), "=r"(r3),
                   "=r"(r4), "=r"(r5), "=r"(r6), "=r"(r7)
                 : "l"(p));
    F8 o;
    o.v[0] = __uint_as_float(r0); o.v[1] = __uint_as_float(r1);
    o.v[2] = __uint_as_float(r2); o.v[3] = __uint_as_float(r3);
    o.v[4] = __uint_as_float(r4); o.v[5] = __uint_as_float(r5);
    o.v[6] = __uint_as_float(r6); o.v[7] = __uint_as_float(r7);
    return o;
}

// ============================================================
// Kernel 1: per-batch stats + mask scan + rf + pack (R,I). grid=16, block=1024
// ============================================================
__global__ void __launch_bounds__(1024) pack_kernel(
    const float* __restrict__ fC, const float* __restrict__ fA,
    const float* __restrict__ fD, const float* __restrict__ fB,
    const int* __restrict__ mask)
{
    const int b = blockIdx.x;
    const int tid = threadIdx.x;
    const int lane = tid & 31, warp = tid >> 5;
    const float* ptr[4] = {fC + b*KI, fA + b*KI, fD + b*KI, fB + b*KI};

    // --- stats: sum & sumsq for 4 features ---
    float acc[8];
#pragma unroll
    for (int i = 0; i < 8; i++) acc[i] = 0.f;
    for (int j = tid; j < KI/4; j += 1024) {
#pragma unroll
        for (int f = 0; f < 4; f++) {
            float4 v = ((const float4*)ptr[f])[j];
            acc[2*f]   += (v.x + v.y) + (v.z + v.w);
            acc[2*f+1] += (v.x*v.x + v.y*v.y) + (v.z*v.z + v.w*v.w);
        }
    }
#pragma unroll
    for (int off = 16; off; off >>= 1)
#pragma unroll
        for (int i = 0; i < 8; i++)
            acc[i] += __shfl_down_sync(0xffffffffu, acc[i], off);

    __shared__ float red[8][32];
    if (lane == 0)
#pragma unroll
        for (int i = 0; i < 8; i++) red[i][warp] = acc[i];
    __syncthreads();

    __shared__ float s_mu[4], s_inv[4];
    if (tid < 32) {
#pragma unroll
        for (int i = 0; i < 8; i++) acc[i] = red[i][tid];
#pragma unroll
        for (int off = 16; off; off >>= 1)
#pragma unroll
            for (int i = 0; i < 8; i++)
                acc[i] += __shfl_down_sync(0xffffffffu, acc[i], off);
        if (tid == 0) {
#pragma unroll
            for (int f = 0; f < 4; f++) {
                float mu = acc[2*f] * (1.f / KI);
                float var = acc[2*f+1] * (1.f / KI) - mu * mu;
                float sd = sqrtf(fmaxf(var, 0.f));
                s_mu[f] = mu;
                s_inv[f] = 1.f / (sd + EPS_C);
            }
        }
    }
    __syncthreads();

    // --- mask scan ---
    const int base = b * KF + tid * 32;
    int mbits[32];
    int cnt = 0;
#pragma unroll
    for (int i = 0; i < 32; i += 4) {
        int4 mm = *(const int4*)(mask + base + i);
        mbits[i] = mm.x; mbits[i+1] = mm.y; mbits[i+2] = mm.z; mbits[i+3] = mm.w;
        cnt += mm.x + mm.y + mm.z + mm.w;
    }
    int inc = cnt;
#pragma unroll
    for (int off = 1; off < 32; off <<= 1) {
        int v = __shfl_up_sync(0xffffffffu, inc, off);
        if (lane >= off) inc += v;
    }
    __shared__ int wsum[32];
    if (lane == 31) wsum[warp] = inc;
    __syncthreads();
    if (tid < 32) {
        int v = wsum[tid];
        int ssum = v;
#pragma unroll
        for (int off = 1; off < 32; off <<= 1) {
            int u = __shfl_up_sync(0xffffffffu, ssum, off);
            if (tid >= off) ssum += u;
        }
        wsum[tid] = ssum - v;
    }
    __syncthreads();
    int r = wsum[warp] + inc - cnt;   // rank of first image position in this thread's chunk

    const float mu0 = s_mu[0], iv0 = s_inv[0];
    const float mu1 = s_mu[1], iv1 = s_inv[1];
    const float mu2 = s_mu[2], iv2 = s_inv[2];
    const float mu3 = s_mu[3], iv3 = s_inv[3];

    float4* RIp = (float4*)(g_RI + (size_t)base * 2);   // 2 floats per position
#pragma unroll
    for (int c = 0; c < 8; c++) {
        float rv[4], iv[4];
#pragma unroll
        for (int e = 0; e < 4; e++) {
            if (mbits[c*4 + e]) {
                float zc = (ptr[0][r] - mu0) * iv0;
                float za = (ptr[1][r] - mu1) * iv1;
                float zd = (ptr[2][r] - mu2) * iv2;
                float zb = (ptr[3][r] - mu3) * iv3;
                float Ct = fmaxf(zc, 0.f);
                float At = 1.f / (1.f + fast_ex2(-za * L2E));
                float Dt = 1.f / (1.f + fast_ex2(-zd * L2E));
                float Bt = 1.f / (1.f + fast_ex2(-zb * L2E));
                float denom = fmaxf(1.f + 0.5f * (Dt + Bt), EPS_C);
                rv[e] = Ct * At / denom;
                iv[e] = 1.f;
                r++;
            } else {
                rv[e] = 0.f; iv[e] = 0.f;
            }
        }
        RIp[c*2]     = make_float4(rv[0], iv[0], rv[1], iv[1]);
        RIp[c*2 + 1] = make_float4(rv[2], iv[2], rv[3], iv[3]);
    }
}

// ============================================================
// Kernel 2: score — 8 heads per block, (R,I) stream loaded once, LDG.256.
// grid = BB * (HH/HPB) * NSEG = 1024, block = 256.
// Each thread: one float8 per head. Per head: zi=Σe·I, p=Σe·R, sm=Σe·min(R,1).
// ============================================================
__global__ void __launch_bounds__(256) score_kernel(const float* __restrict__ attn)
{
    const int bx  = blockIdx.x;
    const int b   = bx >> 6;             // / 64
    const int hg  = (bx >> 4) & 3;
    const int seg = bx & 15;
    const int tid = threadIdx.x;

    const int row0 = b * HH + hg * HPB;
    const int i8 = seg * 256 + tid;                 // float8 index within row (4096/row)
    const float* A0 = attn + (size_t)row0 * KF + (size_t)i8 * 8;
    const float4* RIf4 = (const float4*)(g_RI + (size_t)b * KF * 2) + (size_t)i8 * 4;

    // weight vectors for this thread's 8 positions
    float R[8], I[8], M[8];
#pragma unroll
    for (int c = 0; c < 4; c++) {
        float4 ri = RIf4[c];
        R[2*c]   = ri.x; I[2*c]   = ri.y;
        R[2*c+1] = ri.z; I[2*c+1] = ri.w;
        M[2*c]   = fminf(ri.x, 1.f);
        M[2*c+1] = fminf(ri.z, 1.f);
    }

    float zi[HPB], p[HPB], sm[HPB];
#pragma unroll
    for (int h = 0; h < HPB; h++) { zi[h] = 0.f; p[h] = 0.f; sm[h] = 0.f; }

#pragma unroll
    for (int h = 0; h < HPB; h++) {
        F8 x = ldg256_evict_last(A0 + (size_t)h * KF);
#pragma unroll
        for (int e = 0; e < 8; e++) {
            float ev = fast_ex2(x.v[e] * L2E);
            zi[h] = fmaf(ev, I[e], zi[h]);
            p[h]  = fmaf(ev, R[e], p[h]);
            sm[h] = fmaf(ev, M[e], sm[h]);
        }
    }

    // intra-warp reduce all 24 accumulators
#pragma unroll
    for (int off = 16; off; off >>= 1) {
#pragma unroll
        for (int h = 0; h < HPB; h++) {
            zi[h] += __shfl_down_sync(0xffffffffu, zi[h], off);
            p[h]  += __shfl_down_sync(0xffffffffu, p[h],  off);
            sm[h] += __shfl_down_sync(0xffffffffu, sm[h], off);
        }
    }
    __shared__ float sred[8][HPB][3];
    const int lane = tid & 31, warp = tid >> 5;
    if (lane == 0) {
#pragma unroll
        for (int h = 0; h < HPB; h++) {
            sred[warp][h][0] = zi[h];
            sred[warp][h][1] = p[h];
            sred[warp][h][2] = sm[h];
        }
    }
    __syncthreads();
    if (tid < HPB) {
        float a0 = 0.f, a1 = 0.f, a2 = 0.f;
#pragma unroll
        for (int w = 0; w < 8; w++) {
            a0 += sred[w][tid][0];
            a1 += sred[w][tid][1];
            a2 += sred[w][tid][2];
        }
        float4* dst = (float4*)(g_part + (size_t)((row0 + tid) * NSEG + seg) * 4);
        *dst = make_float4(a0, a1, a2, 0.f);
    }
}

// ============================================================
// Kernel 3: finalize + warp-argmax top-7 per batch. grid=1, block=512
// ============================================================
__global__ void __launch_bounds__(512) select_kernel()
{
    const int tid = threadIdx.x;       // tid == row == b*32 + h
    const int lane = tid & 31;

    // finalize: fixed-order combine of NSEG partials
    const float4* pp = (const float4*)(g_part + (size_t)tid * NSEG * 4);
    float zi = 0.f, p = 0.f, sm = 0.f;
#pragma unroll
    for (int k = 0; k < NSEG; k++) {
        float4 v = pp[k];
        zi += v.x; p += v.y; sm += v.z;
    }
    const float sp = p / zi;
    const float sn = (zi - sm) / zi;

    // top-7 on sp within warp (lane = head); strict >, lowest index wins ties
    bool sel = false;
#pragma unroll
    for (int t = 0; t < 7; t++) {
        float cv = sel ? -FLT_MAX : sp;
        int ci = lane;
#pragma unroll
        for (int off = 16; off; off >>= 1) {
            float ov = __shfl_down_sync(0xffffffffu, cv, off);
            int   oi = __shfl_down_sync(0xffffffffu, ci, off);
            if (ov > cv || (ov == cv && oi < ci)) { cv = ov; ci = oi; }
        }
        int win = __shfl_sync(0xffffffffu, ci, 0);
        if (lane == win) sel = true;
    }
    const bool mpos = sel && (sp > 0.f);

    // top-7 on sn with m_pos heads masked out
    const float ns = mpos ? -FLT_MAX : sn;
    sel = false;
#pragma unroll
    for (int t = 0; t < 7; t++) {
        float cv = sel ? -FLT_MAX : ns;
        int ci = lane;
#pragma unroll
        for (int off = 16; off; off >>= 1) {
            float ov = __shfl_down_sync(0xffffffffu, cv, off);
            int   oi = __shfl_down_sync(0xffffffffu, ci, off);
            if (ov > cv || (ov == cv && oi < ci)) { cv = ov; ci = oi; }
        }
        int win = __shfl_sync(0xffffffffu, ci, 0);
        if (lane == win) sel = true;
    }
    const bool mneg = sel && (ns > 0.f);   // mpos heads have ns=-FLT_MAX, never >0

    g_ca[tid] = mpos ? GAMMA_C : 0.f;
    g_cb[tid] = mneg ? GAMMA_C : 0.f;
}

// ============================================================
// Kernel 4: out = attn + a*R - c*W,  W = max(1-R,0)*I.
// grid = NROW*16 = 8192, block=256. attn via ldcs (L2-warm), out via stcs.
// ============================================================
__global__ void __launch_bounds__(256) apply_kernel(const float* __restrict__ attn,
                                                    float* __restrict__ out)
{
    const int bh   = blockIdx.x >> 4;
    const int seg  = blockIdx.x & 15;
    const int base = bh * 8192 + seg * 512 + threadIdx.x;
    const int b    = bh >> 5;

    const float4* Ap = (const float4*)attn;
    float4* Op = (float4*)out;

    float4 x0 = __ldcs(&Ap[base]);
    float4 x1 = __ldcs(&Ap[base + 256]);
    float a = g_ca[bh];
    float c = g_cb[bh];

    if (a == 0.f && c == 0.f) {
        __stcs(&Op[base], x0);
        __stcs(&Op[base + 256], x1);
        return;
    }

    const int pidx = seg * 512 + threadIdx.x;   // float4-of-positions index
    const float4* RIf4 = (const float4*)(g_RI + (size_t)b * KF * 2);
    float4 ra = RIf4[2*pidx];
    float4 rb = RIf4[2*pidx + 1];
    float4 rc = RIf4[2*(pidx + 256)];
    float4 rd = RIf4[2*(pidx + 256) + 1];

    float4 o0, o1;
    {
        float R, I, w;
        R = ra.x; I = ra.y; w = fmaxf(1.f - R, 0.f) * I;
        o0.x = fmaf(a, R, fmaf(-c, w, x0.x));
        R = ra.z; I = ra.w; w = fmaxf(1.f - R, 0.f) * I;
        o0.y = fmaf(a, R, fmaf(-c, w, x0.y));
        R = rb.x; I = rb.y; w = fmaxf(1.f - R, 0.f) * I;
        o0.z = fmaf(a, R, fmaf(-c, w, x0.z));
        R = rb.z; I = rb.w; w = fmaxf(1.f - R, 0.f) * I;
        o0.w = fmaf(a, R, fmaf(-c, w, x0.w));
        R = rc.x; I = rc.y; w = fmaxf(1.f - R, 0.f) * I;
        o1.x = fmaf(a, R, fmaf(-c, w, x1.x));
        R = rc.z; I = rc.w; w = fmaxf(1.f - R, 0.f) * I;
        o1.y = fmaf(a, R, fmaf(-c, w, x1.y));
        R = rd.x; I = rd.y; w = fmaxf(1.f - R, 0.f) * I;
        o1.z = fmaf(a, R, fmaf(-c, w, x1.z));
        R = rd.z; I = rd.w; w = fmaxf(1.f - R, 0.f) * I;
        o1.w = fmaf(a, R, fmaf(-c, w, x1.w));
    }
    __stcs(&Op[base], o0);
    __stcs(&Op[base + 256], o1);
}

// ============================================================
extern "C" void kernel_launch(void* const* d_in, const int* in_sizes, int n_in,
                              void* d_out, int out_size)
{
    const float* attn = (const float*)d_in[0];
    const int*   mask = (const int*)  d_in[1];
    const float* fC   = (const float*)d_in[2];
    const float* fA   = (const float*)d_in[3];
    const float* fD   = (const float*)d_in[4];
    const float* fB   = (const float*)d_in[5];
    float* out = (float*)d_out;

    pack_kernel<<<BB, 1024>>>(fC, fA, fD, fB, mask);
    score_kernel<<<BB * (HH/HPB) * NSEG, 256>>>(attn);
    select_kernel<<<1, 512>>>();
    apply_kernel<<<NROW * 16, 256>>>(attn, out);
}

// round 12
// speedup vs baseline: 1.1491x; 1.0101x over previous
#include <cuda_runtime.h>
#include <math.h>
#include <float.h>

#define KF 32768
#define KI 16384
#define BB 16
#define HH 32
#define NROW (BB*HH)
#define NSEG 16                // score segments per row
#define HPB 8                  // heads per score block
#define GAMMA_C 0.3f
#define EPS_C 1e-6f
#define L2E 1.4426950408889634f

// ---- scratch (static device arrays; no allocations) ----
__device__ float g_RI[BB * KF * 2];        // interleaved (rf, indicator) per position
__device__ float g_part[NROW * NSEG * 4];  // per (row,seg): zi, p, sm, pad
__device__ float g_ca[NROW];               // GAMMA * m_pos
__device__ float g_cb[NROW];               // GAMMA * m_neg

__device__ __forceinline__ float fast_ex2(float x) {
    float y;
    asm("ex2.approx.ftz.f32 %0, %1;" : "=f"(y) : "f"(x));
    return y;
}

struct F8 { float v[8]; };

// 256-bit global load with L2 evict_last (legal form: .v8.b32)
__device__ __forceinline__ F8 ldg256_evict_last(const float* p) {
    unsigned r0, r1, r2, r3, r4, r5, r6, r7;
    asm volatile("ld.global.L2::evict_last.v8.b32 {%0,%1,%2,%3,%4,%5,%6,%7}, [%8];"
                 : "=r"(r0), "=r"(r1), "=r"(r2), "=r"(r3),
                   "=r"(r4), "=r"(r5), "=r"(r6), "=r"(r7)
                 : "l"(p));
    F8 o;
    o.v[0] = __uint_as_float(r0); o.v[1] = __uint_as_float(r1);
    o.v[2] = __uint_as_float(r2); o.v[3] = __uint_as_float(r3);
    o.v[4] = __uint_as_float(r4); o.v[5] = __uint_as_float(r5);
    o.v[6] = __uint_as_float(r6); o.v[7] = __uint_as_float(r7);
    return o;
}

// ============================================================
// Kernel 1: per-batch stats + mask scan + rf + pack (R,I). grid=16, block=1024
// ============================================================
__global__ void __launch_bounds__(1024) pack_kernel(
    const float* __restrict__ fC, const float* __restrict__ fA,
    const float* __restrict__ fD, const float* __restrict__ fB,
    const int* __restrict__ mask)
{
    const int b = blockIdx.x;
    const int tid = threadIdx.x;
    const int lane = tid & 31, warp = tid >> 5;
    const float* ptr[4] = {fC + b*KI, fA + b*KI, fD + b*KI, fB + b*KI};

    // --- stats: sum & sumsq for 4 features ---
    float acc[8];
#pragma unroll
    for (int i = 0; i < 8; i++) acc[i] = 0.f;
    for (int j = tid; j < KI/4; j += 1024) {
#pragma unroll
        for (int f = 0; f < 4; f++) {
            float4 v = ((const float4*)ptr[f])[j];
            acc[2*f]   += (v.x + v.y) + (v.z + v.w);
            acc[2*f+1] += (v.x*v.x + v.y*v.y) + (v.z*v.z + v.w*v.w);
        }
    }
#pragma unroll
    for (int off = 16; off; off >>= 1)
#pragma unroll
        for (int i = 0; i < 8; i++)
            acc[i] += __shfl_down_sync(0xffffffffu, acc[i], off);

    __shared__ float red[8][32];
    if (lane == 0)
#pragma unroll
        for (int i = 0; i < 8; i++) red[i][warp] = acc[i];
    __syncthreads();

    __shared__ float s_mu[4], s_inv[4];
    if (tid < 32) {
#pragma unroll
        for (int i = 0; i < 8; i++) acc[i] = red[i][tid];
#pragma unroll
        for (int off = 16; off; off >>= 1)
#pragma unroll
            for (int i = 0; i < 8; i++)
                acc[i] += __shfl_down_sync(0xffffffffu, acc[i], off);
        if (tid == 0) {
#pragma unroll
            for (int f = 0; f < 4; f++) {
                float mu = acc[2*f] * (1.f / KI);
                float var = acc[2*f+1] * (1.f / KI) - mu * mu;
                float sd = sqrtf(fmaxf(var, 0.f));
                s_mu[f] = mu;
                s_inv[f] = 1.f / (sd + EPS_C);
            }
        }
    }
    __syncthreads();

    // --- mask scan ---
    const int base = b * KF + tid * 32;
    int mbits[32];
    int cnt = 0;
#pragma unroll
    for (int i = 0; i < 32; i += 4) {
        int4 mm = *(const int4*)(mask + base + i);
        mbits[i] = mm.x; mbits[i+1] = mm.y; mbits[i+2] = mm.z; mbits[i+3] = mm.w;
        cnt += mm.x + mm.y + mm.z + mm.w;
    }
    int inc = cnt;
#pragma unroll
    for (int off = 1; off < 32; off <<= 1) {
        int v = __shfl_up_sync(0xffffffffu, inc, off);
        if (lane >= off) inc += v;
    }
    __shared__ int wsum[32];
    if (lane == 31) wsum[warp] = inc;
    __syncthreads();
    if (tid < 32) {
        int v = wsum[tid];
        int ssum = v;
#pragma unroll
        for (int off = 1; off < 32; off <<= 1) {
            int u = __shfl_up_sync(0xffffffffu, ssum, off);
            if (tid >= off) ssum += u;
        }
        wsum[tid] = ssum - v;
    }
    __syncthreads();
    int r = wsum[warp] + inc - cnt;   // rank of first image position in this thread's chunk

    const float mu0 = s_mu[0], iv0 = s_inv[0];
    const float mu1 = s_mu[1], iv1 = s_inv[1];
    const float mu2 = s_mu[2], iv2 = s_inv[2];
    const float mu3 = s_mu[3], iv3 = s_inv[3];

    float4* RIp = (float4*)(g_RI + (size_t)base * 2);   // 2 floats per position
#pragma unroll
    for (int c = 0; c < 8; c++) {
        float rv[4], iv[4];
#pragma unroll
        for (int e = 0; e < 4; e++) {
            if (mbits[c*4 + e]) {
                float zc = (ptr[0][r] - mu0) * iv0;
                float za = (ptr[1][r] - mu1) * iv1;
                float zd = (ptr[2][r] - mu2) * iv2;
                float zb = (ptr[3][r] - mu3) * iv3;
                float Ct = fmaxf(zc, 0.f);
                float At = 1.f / (1.f + fast_ex2(-za * L2E));
                float Dt = 1.f / (1.f + fast_ex2(-zd * L2E));
                float Bt = 1.f / (1.f + fast_ex2(-zb * L2E));
                float denom = fmaxf(1.f + 0.5f * (Dt + Bt), EPS_C);
                rv[e] = Ct * At / denom;
                iv[e] = 1.f;
                r++;
            } else {
                rv[e] = 0.f; iv[e] = 0.f;
            }
        }
        RIp[c*2]     = make_float4(rv[0], iv[0], rv[1], iv[1]);
        RIp[c*2 + 1] = make_float4(rv[2], iv[2], rv[3], iv[3]);
    }
}

// ============================================================
// Kernel 2: score — 8 heads per block, (R,I) stream loaded once, LDG.256.
// grid = BB * (HH/HPB) * NSEG = 1024, block = 256.
// Each thread: one float8 per head. Per head: zi=Σe·I, p=Σe·R, sm=Σe·min(R,1).
// ============================================================
__global__ void __launch_bounds__(256) score_kernel(const float* __restrict__ attn)
{
    const int bx  = blockIdx.x;
    const int b   = bx >> 6;             // / 64
    const int hg  = (bx >> 4) & 3;
    const int seg = bx & 15;
    const int tid = threadIdx.x;

    const int row0 = b * HH + hg * HPB;
    const int i8 = seg * 256 + tid;                 // float8 index within row (4096/row)
    const float* A0 = attn + (size_t)row0 * KF + (size_t)i8 * 8;
    const float4* RIf4 = (const float4*)(g_RI + (size_t)b * KF * 2) + (size_t)i8 * 4;

    // weight vectors for this thread's 8 positions
    float R[8], I[8], M[8];
#pragma unroll
    for (int c = 0; c < 4; c++) {
        float4 ri = RIf4[c];
        R[2*c]   = ri.x; I[2*c]   = ri.y;
        R[2*c+1] = ri.z; I[2*c+1] = ri.w;
        M[2*c]   = fminf(ri.x, 1.f);
        M[2*c+1] = fminf(ri.z, 1.f);
    }

    float zi[HPB], p[HPB], sm[HPB];
#pragma unroll
    for (int h = 0; h < HPB; h++) { zi[h] = 0.f; p[h] = 0.f; sm[h] = 0.f; }

#pragma unroll
    for (int h = 0; h < HPB; h++) {
        F8 x = ldg256_evict_last(A0 + (size_t)h * KF);
#pragma unroll
        for (int e = 0; e < 8; e++) {
            float ev = fast_ex2(x.v[e] * L2E);
            zi[h] = fmaf(ev, I[e], zi[h]);
            p[h]  = fmaf(ev, R[e], p[h]);
            sm[h] = fmaf(ev, M[e], sm[h]);
        }
    }

    // intra-warp reduce all 24 accumulators
#pragma unroll
    for (int off = 16; off; off >>= 1) {
#pragma unroll
        for (int h = 0; h < HPB; h++) {
            zi[h] += __shfl_down_sync(0xffffffffu, zi[h], off);
            p[h]  += __shfl_down_sync(0xffffffffu, p[h],  off);
            sm[h] += __shfl_down_sync(0xffffffffu, sm[h], off);
        }
    }
    __shared__ float sred[8][HPB][3];
    const int lane = tid & 31, warp = tid >> 5;
    if (lane == 0) {
#pragma unroll
        for (int h = 0; h < HPB; h++) {
            sred[warp][h][0] = zi[h];
            sred[warp][h][1] = p[h];
            sred[warp][h][2] = sm[h];
        }
    }
    __syncthreads();
    if (tid < HPB) {
        float a0 = 0.f, a1 = 0.f, a2 = 0.f;
#pragma unroll
        for (int w = 0; w < 8; w++) {
            a0 += sred[w][tid][0];
            a1 += sred[w][tid][1];
            a2 += sred[w][tid][2];
        }
        float4* dst = (float4*)(g_part + (size_t)((row0 + tid) * NSEG + seg) * 4);
        *dst = make_float4(a0, a1, a2, 0.f);
    }
}

// ============================================================
// Kernel 3: finalize + warp-argmax top-7 per batch. grid=1, block=512
// ============================================================
__global__ void __launch_bounds__(512) select_kernel()
{
    const int tid = threadIdx.x;       // tid == row == b*32 + h
    const int lane = tid & 31;

    // finalize: fixed-order combine of NSEG partials
    const float4* pp = (const float4*)(g_part + (size_t)tid * NSEG * 4);
    float zi = 0.f, p = 0.f, sm = 0.f;
#pragma unroll
    for (int k = 0; k < NSEG; k++) {
        float4 v = pp[k];
        zi += v.x; p += v.y; sm += v.z;
    }
    const float sp = p / zi;
    const float sn = (zi - sm) / zi;

    // top-7 on sp within warp (lane = head); strict >, lowest index wins ties
    bool sel = false;
#pragma unroll
    for (int t = 0; t < 7; t++) {
        float cv = sel ? -FLT_MAX : sp;
        int ci = lane;
#pragma unroll
        for (int off = 16; off; off >>= 1) {
            float ov = __shfl_down_sync(0xffffffffu, cv, off);
            int   oi = __shfl_down_sync(0xffffffffu, ci, off);
            if (ov > cv || (ov == cv && oi < ci)) { cv = ov; ci = oi; }
        }
        int win = __shfl_sync(0xffffffffu, ci, 0);
        if (lane == win) sel = true;
    }
    const bool mpos = sel && (sp > 0.f);

    // top-7 on sn with m_pos heads masked out
    const float ns = mpos ? -FLT_MAX : sn;
    sel = false;
#pragma unroll
    for (int t = 0; t < 7; t++) {
        float cv = sel ? -FLT_MAX : ns;
        int ci = lane;
#pragma unroll
        for (int off = 16; off; off >>= 1) {
            float ov = __shfl_down_sync(0xffffffffu, cv, off);
            int   oi = __shfl_down_sync(0xffffffffu, ci, off);
            if (ov > cv || (ov == cv && oi < ci)) { cv = ov; ci = oi; }
        }
        int win = __shfl_sync(0xffffffffu, ci, 0);
        if (lane == win) sel = true;
    }
    const bool mneg = sel && (ns > 0.f);   // mpos heads have ns=-FLT_MAX, never >0

    g_ca[tid] = mpos ? GAMMA_C : 0.f;
    g_cb[tid] = mneg ? GAMMA_C : 0.f;
}

// ============================================================
// Kernel 4: out = attn + a*R - c*W,  W = max(1-R,0)*I.
// grid = NROW*16 = 8192, block=256. attn via ldcs (L2-warm), out via stcs.
// ============================================================
__global__ void __launch_bounds__(256) apply_kernel(const float* __restrict__ attn,
                                                    float* __restrict__ out)
{
    const int bh   = blockIdx.x >> 4;
    const int seg  = blockIdx.x & 15;
    const int base = bh * 8192 + seg * 512 + threadIdx.x;
    const int b    = bh >> 5;

    const float4* Ap = (const float4*)attn;
    float4* Op = (float4*)out;

    float4 x0 = __ldcs(&Ap[base]);
    float4 x1 = __ldcs(&Ap[base + 256]);
    float a = g_ca[bh];
    float c = g_cb[bh];

    if (a == 0.f && c == 0.f) {
        __stcs(&Op[base], x0);
        __stcs(&Op[base + 256], x1);
        return;
    }

    const int pidx = seg * 512 + threadIdx.x;   // float4-of-positions index
    const float4* RIf4 = (const float4*)(g_RI + (size_t)b * KF * 2);
    float4 ra = RIf4[2*pidx];
    float4 rb = RIf4[2*pidx + 1];
    float4 rc = RIf4[2*(pidx + 256)];
    float4 rd = RIf4[2*(pidx + 256) + 1];

    float4 o0, o1;
    {
        float R, I, w;
        R = ra.x; I = ra.y; w = fmaxf(1.f - R, 0.f) * I;
        o0.x = fmaf(a, R, fmaf(-c, w, x0.x));
        R = ra.z; I = ra.w; w = fmaxf(1.f - R, 0.f) * I;
        o0.y = fmaf(a, R, fmaf(-c, w, x0.y));
        R = rb.x; I = rb.y; w = fmaxf(1.f - R, 0.f) * I;
        o0.z = fmaf(a, R, fmaf(-c, w, x0.z));
        R = rb.z; I = rb.w; w = fmaxf(1.f - R, 0.f) * I;
        o0.w = fmaf(a, R, fmaf(-c, w, x0.w));
        R = rc.x; I = rc.y; w = fmaxf(1.f - R, 0.f) * I;
        o1.x = fmaf(a, R, fmaf(-c, w, x1.x));
        R = rc.z; I = rc.w; w = fmaxf(1.f - R, 0.f) * I;
        o1.y = fmaf(a, R, fmaf(-c, w, x1.y));
        R = rd.x; I = rd.y; w = fmaxf(1.f - R, 0.f) * I;
        o1.z = fmaf(a, R, fmaf(-c, w, x1.z));
        R = rd.z; I = rd.w; w = fmaxf(1.f - R, 0.f) * I;
        o1.w = fmaf(a, R, fmaf(-c, w, x1.w));
    }
    __stcs(&Op[base], o0);
    __stcs(&Op[base + 256], o1);
}

// ============================================================
extern "C" void kernel_launch(void* const* d_in, const int* in_sizes, int n_in,
                              void* d_out, int out_size)
{
    const float* attn = (const float*)d_in[0];
    const int*   mask = (const int*)  d_in[1];
    const float* fC   = (const float*)d_in[2];
    const float* fA   = (const float*)d_in[3];
    const float* fD   = (const float*)d_in[4];
    const float* fB   = (const float*)d_in[5];
    float* out = (float*)d_out;

    pack_kernel<<<BB, 1024>>>(fC, fA, fD, fB, mask);
    score_kernel<<<BB * (HH/HPB) * NSEG, 256>>>(attn);
    select_kernel<<<1, 512>>>();
    apply_kernel<<<NROW * 16, 256>>>(attn, out);
}

// round 13
// speedup vs baseline: 1.1495x; 1.0004x over previous
#include <cuda_runtime.h>
#include <math.h>
#include <float.h>

#define KF 32768
#define KI 16384
#define BB 16
#define HH 32
#define NROW (BB*HH)
#define NSEG 16                // score segments per row
#define HPB 8                  // heads per score block
#define GAMMA_C 0.3f
#define EPS_C 1e-6f
#define L2E 1.4426950408889634f

// ---- scratch (static device arrays; no allocations) ----
__device__ float g_RI[BB * KF * 2];        // interleaved (rf, indicator) per position
__device__ float g_part[NROW * NSEG * 4];  // per (row,seg): zi, p, sm, pad
__device__ float g_ca[NROW];               // GAMMA * m_pos
__device__ float g_cb[NROW];               // GAMMA * m_neg

__device__ __forceinline__ float fast_ex2(float x) {
    float y;
    asm("ex2.approx.ftz.f32 %0, %1;" : "=f"(y) : "f"(x));
    return y;
}

struct F8 { float v[8]; };

// 256-bit global load with L2 evict_last (legal form: .v8.b32)
__device__ __forceinline__ F8 ldg256_evict_last(const float* p) {
    unsigned r0, r1, r2, r3, r4, r5, r6, r7;
    asm volatile("ld.global.L2::evict_last.v8.b32 {%0,%1,%2,%3,%4,%5,%6,%7}, [%8];"
                 : "=r"(r0), "=r"(r1), "=r"(r2), "=r"(r3),
                   "=r"(r4), "=r"(r5), "=r"(r6), "=r"(r7)
                 : "l"(p));
    F8 o;
    o.v[0] = __uint_as_float(r0); o.v[1] = __uint_as_float(r1);
    o.v[2] = __uint_as_float(r2); o.v[3] = __uint_as_float(r3);
    o.v[4] = __uint_as_float(r4); o.v[5] = __uint_as_float(r5);
    o.v[6] = __uint_as_float(r6); o.v[7] = __uint_as_float(r7);
    return o;
}

// ============================================================
// Kernel 1: per-batch stats + mask scan + rf + pack (R,I). grid=16, block=1024
// ============================================================
__global__ void __launch_bounds__(1024) pack_kernel(
    const float* __restrict__ fC, const float* __restrict__ fA,
    const float* __restrict__ fD, const float* __restrict__ fB,
    const int* __restrict__ mask)
{
    const int b = blockIdx.x;
    const int tid = threadIdx.x;
    const int lane = tid & 31, warp = tid >> 5;
    const float* ptr[4] = {fC + b*KI, fA + b*KI, fD + b*KI, fB + b*KI};

    // --- stats: sum & sumsq for 4 features ---
    float acc[8];
#pragma unroll
    for (int i = 0; i < 8; i++) acc[i] = 0.f;
    for (int j = tid; j < KI/4; j += 1024) {
#pragma unroll
        for (int f = 0; f < 4; f++) {
            float4 v = ((const float4*)ptr[f])[j];
            acc[2*f]   += (v.x + v.y) + (v.z + v.w);
            acc[2*f+1] += (v.x*v.x + v.y*v.y) + (v.z*v.z + v.w*v.w);
        }
    }
#pragma unroll
    for (int off = 16; off; off >>= 1)
#pragma unroll
        for (int i = 0; i < 8; i++)
            acc[i] += __shfl_down_sync(0xffffffffu, acc[i], off);

    __shared__ float red[8][32];
    if (lane == 0)
#pragma unroll
        for (int i = 0; i < 8; i++) red[i][warp] = acc[i];
    __syncthreads();

    __shared__ float s_mu[4], s_inv[4];
    if (tid < 32) {
#pragma unroll
        for (int i = 0; i < 8; i++) acc[i] = red[i][tid];
#pragma unroll
        for (int off = 16; off; off >>= 1)
#pragma unroll
            for (int i = 0; i < 8; i++)
                acc[i] += __shfl_down_sync(0xffffffffu, acc[i], off);
        if (tid == 0) {
#pragma unroll
            for (int f = 0; f < 4; f++) {
                float mu = acc[2*f] * (1.f / KI);
                float var = acc[2*f+1] * (1.f / KI) - mu * mu;
                float sd = sqrtf(fmaxf(var, 0.f));
                s_mu[f] = mu;
                s_inv[f] = 1.f / (sd + EPS_C);
            }
        }
    }
    __syncthreads();

    // --- mask scan ---
    const int base = b * KF + tid * 32;
    int mbits[32];
    int cnt = 0;
#pragma unroll
    for (int i = 0; i < 32; i += 4) {
        int4 mm = *(const int4*)(mask + base + i);
        mbits[i] = mm.x; mbits[i+1] = mm.y; mbits[i+2] = mm.z; mbits[i+3] = mm.w;
        cnt += mm.x + mm.y + mm.z + mm.w;
    }
    int inc = cnt;
#pragma unroll
    for (int off = 1; off < 32; off <<= 1) {
        int v = __shfl_up_sync(0xffffffffu, inc, off);
        if (lane >= off) inc += v;
    }
    __shared__ int wsum[32];
    if (lane == 31) wsum[warp] = inc;
    __syncthreads();
    if (tid < 32) {
        int v = wsum[tid];
        int ssum = v;
#pragma unroll
        for (int off = 1; off < 32; off <<= 1) {
            int u = __shfl_up_sync(0xffffffffu, ssum, off);
            if (tid >= off) ssum += u;
        }
        wsum[tid] = ssum - v;
    }
    __syncthreads();
    int r = wsum[warp] + inc - cnt;   // rank of first image position in this thread's chunk

    const float mu0 = s_mu[0], iv0 = s_inv[0];
    const float mu1 = s_mu[1], iv1 = s_inv[1];
    const float mu2 = s_mu[2], iv2 = s_inv[2];
    const float mu3 = s_mu[3], iv3 = s_inv[3];

    float4* RIp = (float4*)(g_RI + (size_t)base * 2);   // 2 floats per position
#pragma unroll
    for (int c = 0; c < 8; c++) {
        float rv[4], iv[4];
#pragma unroll
        for (int e = 0; e < 4; e++) {
            if (mbits[c*4 + e]) {
                float zc = (ptr[0][r] - mu0) * iv0;
                float za = (ptr[1][r] - mu1) * iv1;
                float zd = (ptr[2][r] - mu2) * iv2;
                float zb = (ptr[3][r] - mu3) * iv3;
                float Ct = fmaxf(zc, 0.f);
                float At = 1.f / (1.f + fast_ex2(-za * L2E));
                float Dt = 1.f / (1.f + fast_ex2(-zd * L2E));
                float Bt = 1.f / (1.f + fast_ex2(-zb * L2E));
                float denom = fmaxf(1.f + 0.5f * (Dt + Bt), EPS_C);
                rv[e] = Ct * At / denom;
                iv[e] = 1.f;
                r++;
            } else {
                rv[e] = 0.f; iv[e] = 0.f;
            }
        }
        RIp[c*2]     = make_float4(rv[0], iv[0], rv[1], iv[1]);
        RIp[c*2 + 1] = make_float4(rv[2], iv[2], rv[3], iv[3]);
    }
}

// ============================================================
// Kernel 2: score — 8 heads per block, (R,I) stream loaded once, LDG.256.
// grid = BB * (HH/HPB) * NSEG = 1024, block = 256.
// Each thread: one float8 per head. Per head: zi=Σe·I, p=Σe·R, sm=Σe·min(R,1).
// ============================================================
__global__ void __launch_bounds__(256) score_kernel(const float* __restrict__ attn)
{
    const int bx  = blockIdx.x;
    const int b   = bx >> 6;             // / 64
    const int hg  = (bx >> 4) & 3;
    const int seg = bx & 15;
    const int tid = threadIdx.x;

    const int row0 = b * HH + hg * HPB;
    const int i8 = seg * 256 + tid;                 // float8 index within row (4096/row)
    const float* A0 = attn + (size_t)row0 * KF + (size_t)i8 * 8;
    const float4* RIf4 = (const float4*)(g_RI + (size_t)b * KF * 2) + (size_t)i8 * 4;

    // weight vectors for this thread's 8 positions
    float R[8], I[8], M[8];
#pragma unroll
    for (int c = 0; c < 4; c++) {
        float4 ri = RIf4[c];
        R[2*c]   = ri.x; I[2*c]   = ri.y;
        R[2*c+1] = ri.z; I[2*c+1] = ri.w;
        M[2*c]   = fminf(ri.x, 1.f);
        M[2*c+1] = fminf(ri.z, 1.f);
    }

    float zi[HPB], p[HPB], sm[HPB];
#pragma unroll
    for (int h = 0; h < HPB; h++) { zi[h] = 0.f; p[h] = 0.f; sm[h] = 0.f; }

#pragma unroll
    for (int h = 0; h < HPB; h++) {
        F8 x = ldg256_evict_last(A0 + (size_t)h * KF);
#pragma unroll
        for (int e = 0; e < 8; e++) {
            float ev = fast_ex2(x.v[e] * L2E);
            zi[h] = fmaf(ev, I[e], zi[h]);
            p[h]  = fmaf(ev, R[e], p[h]);
            sm[h] = fmaf(ev, M[e], sm[h]);
        }
    }

    // intra-warp reduce all 24 accumulators
#pragma unroll
    for (int off = 16; off; off >>= 1) {
#pragma unroll
        for (int h = 0; h < HPB; h++) {
            zi[h] += __shfl_down_sync(0xffffffffu, zi[h], off);
            p[h]  += __shfl_down_sync(0xffffffffu, p[h],  off);
            sm[h] += __shfl_down_sync(0xffffffffu, sm[h], off);
        }
    }
    __shared__ float sred[8][HPB][3];
    const int lane = tid & 31, warp = tid >> 5;
    if (lane == 0) {
#pragma unroll
        for (int h = 0; h < HPB; h++) {
            sred[warp][h][0] = zi[h];
            sred[warp][h][1] = p[h];
            sred[warp][h][2] = sm[h];
        }
    }
    __syncthreads();
    if (tid < HPB) {
        float a0 = 0.f, a1 = 0.f, a2 = 0.f;
#pragma unroll
        for (int w = 0; w < 8; w++) {
            a0 += sred[w][tid][0];
            a1 += sred[w][tid][1];
            a2 += sred[w][tid][2];
        }
        float4* dst = (float4*)(g_part + (size_t)((row0 + tid) * NSEG + seg) * 4);
        *dst = make_float4(a0, a1, a2, 0.f);
    }
}

// ============================================================
// Kernel 3: finalize + warp-argmax top-7 per batch. grid=1, block=512
// ============================================================
__global__ void __launch_bounds__(512) select_kernel()
{
    const int tid = threadIdx.x;       // tid == row == b*32 + h
    const int lane = tid & 31;

    // finalize: fixed-order combine of NSEG partials
    const float4* pp = (const float4*)(g_part + (size_t)tid * NSEG * 4);
    float zi = 0.f, p = 0.f, sm = 0.f;
#pragma unroll
    for (int k = 0; k < NSEG; k++) {
        float4 v = pp[k];
        zi += v.x; p += v.y; sm += v.z;
    }
    const float sp = p / zi;
    const float sn = (zi - sm) / zi;

    // top-7 on sp within warp (lane = head); strict >, lowest index wins ties
    bool sel = false;
#pragma unroll
    for (int t = 0; t < 7; t++) {
        float cv = sel ? -FLT_MAX : sp;
        int ci = lane;
#pragma unroll
        for (int off = 16; off; off >>= 1) {
            float ov = __shfl_down_sync(0xffffffffu, cv, off);
            int   oi = __shfl_down_sync(0xffffffffu, ci, off);
            if (ov > cv || (ov == cv && oi < ci)) { cv = ov; ci = oi; }
        }
        int win = __shfl_sync(0xffffffffu, ci, 0);
        if (lane == win) sel = true;
    }
    const bool mpos = sel && (sp > 0.f);

    // top-7 on sn with m_pos heads masked out
    const float ns = mpos ? -FLT_MAX : sn;
    sel = false;
#pragma unroll
    for (int t = 0; t < 7; t++) {
        float cv = sel ? -FLT_MAX : ns;
        int ci = lane;
#pragma unroll
        for (int off = 16; off; off >>= 1) {
            float ov = __shfl_down_sync(0xffffffffu, cv, off);
            int   oi = __shfl_down_sync(0xffffffffu, ci, off);
            if (ov > cv || (ov == cv && oi < ci)) { cv = ov; ci = oi; }
        }
        int win = __shfl_sync(0xffffffffu, ci, 0);
        if (lane == win) sel = true;
    }
    const bool mneg = sel && (ns > 0.f);   // mpos heads have ns=-FLT_MAX, never >0

    g_ca[tid] = mpos ? GAMMA_C : 0.f;
    g_cb[tid] = mneg ? GAMMA_C : 0.f;
}

// ============================================================
// Kernel 4: out = attn + a*R - c*W,  W = max(1-R,0)*I.
// grid = NROW*16 = 8192, block=256. attn via ldcs (L2-warm), out via stcs.
// ============================================================
__global__ void __launch_bounds__(256) apply_kernel(const float* __restrict__ attn,
                                                    float* __restrict__ out)
{
    const int bh   = blockIdx.x >> 4;
    const int seg  = blockIdx.x & 15;
    const int base = bh * 8192 + seg * 512 + threadIdx.x;
    const int b    = bh >> 5;

    const float4* Ap = (const float4*)attn;
    float4* Op = (float4*)out;

    float4 x0 = __ldcs(&Ap[base]);
    float4 x1 = __ldcs(&Ap[base + 256]);
    float a = g_ca[bh];
    float c = g_cb[bh];

    if (a == 0.f && c == 0.f) {
        __stcs(&Op[base], x0);
        __stcs(&Op[base + 256], x1);
        return;
    }

    const int pidx = seg * 512 + threadIdx.x;   // float4-of-positions index
    const float4* RIf4 = (const float4*)(g_RI + (size_t)b * KF * 2);
    float4 ra = RIf4[2*pidx];
    float4 rb = RIf4[2*pidx + 1];
    float4 rc = RIf4[2*(pidx + 256)];
    float4 rd = RIf4[2*(pidx + 256) + 1];

    float4 o0, o1;
    {
        float R, I, w;
        R = ra.x; I = ra.y; w = fmaxf(1.f - R, 0.f) * I;
        o0.x = fmaf(a, R, fmaf(-c, w, x0.x));
        R = ra.z; I = ra.w; w = fmaxf(1.f - R, 0.f) * I;
        o0.y = fmaf(a, R, fmaf(-c, w, x0.y));
        R = rb.x; I = rb.y; w = fmaxf(1.f - R, 0.f) * I;
        o0.z = fmaf(a, R, fmaf(-c, w, x0.z));
        R = rb.z; I = rb.w; w = fmaxf(1.f - R, 0.f) * I;
        o0.w = fmaf(a, R, fmaf(-c, w, x0.w));
        R = rc.x; I = rc.y; w = fmaxf(1.f - R, 0.f) * I;
        o1.x = fmaf(a, R, fmaf(-c, w, x1.x));
        R = rc.z; I = rc.w; w = fmaxf(1.f - R, 0.f) * I;
        o1.y = fmaf(a, R, fmaf(-c, w, x1.y));
        R = rd.x; I = rd.y; w = fmaxf(1.f - R, 0.f) * I;
        o1.z = fmaf(a, R, fmaf(-c, w, x1.z));
        R = rd.z; I = rd.w; w = fmaxf(1.f - R, 0.f) * I;
        o1.w = fmaf(a, R, fmaf(-c, w, x1.w));
    }
    __stcs(&Op[base], o0);
    __stcs(&Op[base + 256], o1);
}

// ============================================================
extern "C" void kernel_launch(void* const* d_in, const int* in_sizes, int n_in,
                              void* d_out, int out_size)
{
    const float* attn = (const float*)d_in[0];
    const int*   mask = (const int*)  d_in[1];
    const float* fC   = (const float*)d_in[2];
    const float* fA   = (const float*)d_in[3];
    const float* fD   = (const float*)d_in[4];
    const float* fB   = (const float*)d_in[5];
    float* out = (float*)d_out;

    pack_kernel<<<BB, 1024>>>(fC, fA, fD, fB, mask);
    score_kernel<<<BB * (HH/HPB) * NSEG, 256>>>(attn);
    select_kernel<<<1, 512>>>();
    apply_kernel<<<NROW * 16, 256>>>(attn, out);
}